// round 2
// baseline (speedup 1.0000x reference)
#include <cuda_runtime.h>
#include <cstdint>
#include <cstddef>

// GINConv edge MLP:
//   s = x[src] + x[dst]; h = relu(s@W1^T + b1); out = EPS*(h@W2^T + b2)
// Restructured:
//   Phase 1 (per node):  y[n] = x[n]@W1^T + 0.5*b1        (N x 256)
//   Phase 2 (per edge):  h = relu(y[src]+y[dst]); out = EPS*(h@W2^T + b2)

#define EPS_VAL 0.5f

typedef unsigned long long u64;

// Packed dual-fp32 FMA (Blackwell f32x2 pipe; 2x fp32 rate, bit-exact fp32)
__device__ __forceinline__ u64 ffma2(u64 a, u64 b, u64 c) {
    u64 d;
    asm("fma.rn.f32x2 %0, %1, %2, %3;" : "=l"(d) : "l"(a), "l"(b), "l"(c));
    return d;
}
__device__ __forceinline__ float f2sum(u64 v) {
    float lo = __uint_as_float((unsigned)(v & 0xffffffffu));
    float hi = __uint_as_float((unsigned)(v >> 32));
    return lo + hi;
}

// Scratch: node projections y [N_MAX, 256] (102.4 MB, static device global)
#define N_MAX 100000
__device__ float g_y[(size_t)N_MAX * 256];

// ---------------------------------------------------------------------------
// Kernel 1: y = x @ W1^T + 0.5*b1
// Block tile 64 (n) x 64 (j), K=128 fully resident in smem.
// Warp tile 16x32, lane tile 4x4 (f32x2 pairs over k).
// ---------------------------------------------------------------------------
__global__ __launch_bounds__(256) void node_proj_kernel(
    const float* __restrict__ x, const float* __restrict__ W1,
    const float* __restrict__ b1, int N)
{
    extern __shared__ __align__(16) float sm[];
    float* xs = sm;               // [64][132]
    float* ws = sm + 64 * 132;    // [64][132]
    float* __restrict__ y = g_y;

    const int tid = threadIdx.x;
    const int n0 = blockIdx.x * 64;
    const int j0 = blockIdx.y * 64;

    // Load x panel [64][128] (zero-fill OOB rows)
    #pragma unroll
    for (int it = 0; it < 8; it++) {
        int idx = tid + it * 256;
        int r = idx >> 5;
        int c = (idx & 31) << 2;
        int gr = n0 + r;
        float4 v = make_float4(0.f, 0.f, 0.f, 0.f);
        if (gr < N) v = *(const float4*)(x + (size_t)gr * 128 + c);
        *(float4*)(xs + r * 132 + c) = v;
    }
    // Load W1 panel [64][128]
    #pragma unroll
    for (int it = 0; it < 8; it++) {
        int idx = tid + it * 256;
        int r = idx >> 5;
        int c = (idx & 31) << 2;
        float4 v = *(const float4*)(W1 + (size_t)(j0 + r) * 128 + c);
        *(float4*)(ws + r * 132 + c) = v;
    }
    __syncthreads();

    const int l  = tid & 31, w = tid >> 5;
    const int le = l >> 3,  lo = l & 7;   // 4 x 8 lane grid
    const int we = w & 3,   wo = w >> 2;  // 4 (row) x 2 (col) warp grid

    u64 acc[4][4];
    #pragma unroll
    for (int i = 0; i < 4; i++)
        #pragma unroll
        for (int r = 0; r < 4; r++) acc[i][r] = 0ull;

    const float* xbase = xs + (16 * we + le) * 132;
    const float* wbase = ws + (32 * wo + lo) * 132;

    #pragma unroll 2
    for (int k = 0; k < 128; k += 4) {
        ulonglong2 xa[4], wb[4];
        #pragma unroll
        for (int i = 0; i < 4; i++)
            xa[i] = *(const ulonglong2*)(xbase + (4 * i) * 132 + k);
        #pragma unroll
        for (int r = 0; r < 4; r++)
            wb[r] = *(const ulonglong2*)(wbase + (8 * r) * 132 + k);
        #pragma unroll
        for (int i = 0; i < 4; i++)
            #pragma unroll
            for (int r = 0; r < 4; r++) {
                acc[i][r] = ffma2(xa[i].x, wb[r].x, acc[i][r]);
                acc[i][r] = ffma2(xa[i].y, wb[r].y, acc[i][r]);
            }
    }
    __syncthreads();

    // Stage to smem for coalesced stores
    float* stage = sm;  // [64][68]
    #pragma unroll
    for (int i = 0; i < 4; i++)
        #pragma unroll
        for (int r = 0; r < 4; r++) {
            int rl = 16 * we + le + 4 * i;
            int cl = 32 * wo + lo + 8 * r;
            stage[rl * 68 + cl] = f2sum(acc[i][r]) + 0.5f * b1[j0 + cl];
        }
    __syncthreads();

    #pragma unroll
    for (int it = 0; it < 4; it++) {
        int idx = tid + it * 256;
        int r = idx >> 4;
        int c = (idx & 15) << 2;
        int gr = n0 + r;
        if (gr < N) {
            float4 v = *(float4*)(stage + r * 68 + c);
            *(float4*)(y + (size_t)gr * 256 + j0 + c) = v;
        }
    }
}

// ---------------------------------------------------------------------------
// Kernel 2: per edge-tile of 32: h = relu(y[src]+y[dst]); out = EPS*(h@W2^T+b2)
// Block tile 32 (edges) x 128 (outputs), K=256 reduced in 4 chunks of 64
// (W2 chunk [128][64] staged in smem). Warp tile 16x32, lane tile 4x4.
// ---------------------------------------------------------------------------
__global__ __launch_bounds__(256) void edge_mlp_kernel(
    const int* __restrict__ edge_index,   // int32 [2, E] (harness downcasts int64)
    const float* __restrict__ W2, const float* __restrict__ b2,
    float* __restrict__ out, int E)
{
    extern __shared__ __align__(16) float sm[];
    float* hs  = sm;               // [32][260]
    float* w2s = sm + 32 * 260;    // [128][68]
    const float* __restrict__ y = g_y;

    const int tid = threadIdx.x;
    const int l = tid & 31, w = tid >> 5;
    const int e0 = blockIdx.x * 32;

    // Phase A: gather both endpoints, sum, relu -> hs. One warp handles 4 edges.
    #pragma unroll
    for (int q = 0; q < 4; q++) {
        int row = w * 4 + q;
        int e = e0 + row;
        if (e < E) {
            int s = edge_index[e];
            int d = edge_index[E + e];
            const float* ys = y + (size_t)s * 256;
            const float* yd = y + (size_t)d * 256;
            #pragma unroll
            for (int p = 0; p < 2; p++) {
                int c = (l + 32 * p) << 2;  // 0..252 step 4
                float4 a = *(const float4*)(ys + c);
                float4 b = *(const float4*)(yd + c);
                float4 h;
                h.x = fmaxf(a.x + b.x, 0.f);
                h.y = fmaxf(a.y + b.y, 0.f);
                h.z = fmaxf(a.z + b.z, 0.f);
                h.w = fmaxf(a.w + b.w, 0.f);
                *(float4*)(hs + row * 260 + c) = h;
            }
        }
    }

    const int le = l >> 3, lo = l & 7;   // 4 x 8 lane grid
    const int we = w & 1,  wo = w >> 1;  // 2 (edge) x 4 (out) warp grid

    u64 acc[4][4];
    #pragma unroll
    for (int i = 0; i < 4; i++)
        #pragma unroll
        for (int r = 0; r < 4; r++) acc[i][r] = 0ull;

    const float* hbase = hs + (16 * we + le) * 260;
    const float* wrow  = w2s + (32 * wo + lo) * 68;

    for (int jc = 0; jc < 4; jc++) {
        __syncthreads();  // hs ready (jc==0) / previous w2s chunk fully consumed
        // Load W2 chunk [128 outs][64 j]
        #pragma unroll
        for (int it = 0; it < 8; it++) {
            int idx = tid + it * 256;
            int r = idx >> 4;
            int c = (idx & 15) << 2;
            float4 v = *(const float4*)(W2 + (size_t)r * 256 + jc * 64 + c);
            *(float4*)(w2s + r * 68 + c) = v;
        }
        __syncthreads();

        const float* hc = hbase + jc * 64;
        #pragma unroll 2
        for (int j = 0; j < 64; j += 4) {
            ulonglong2 ha[4], wb[4];
            #pragma unroll
            for (int i = 0; i < 4; i++)
                ha[i] = *(const ulonglong2*)(hc + (4 * i) * 260 + j);
            #pragma unroll
            for (int r = 0; r < 4; r++)
                wb[r] = *(const ulonglong2*)(wrow + (8 * r) * 68 + j);
            #pragma unroll
            for (int i = 0; i < 4; i++)
                #pragma unroll
                for (int r = 0; r < 4; r++) {
                    acc[i][r] = ffma2(ha[i].x, wb[r].x, acc[i][r]);
                    acc[i][r] = ffma2(ha[i].y, wb[r].y, acc[i][r]);
                }
        }
    }
    __syncthreads();

    // Epilogue: bias + EPS scale, stage, coalesced float4 stores
    float* stage = w2s;  // [32][132]
    #pragma unroll
    for (int i = 0; i < 4; i++)
        #pragma unroll
        for (int r = 0; r < 4; r++) {
            int rl = 16 * we + le + 4 * i;
            int cl = 32 * wo + lo + 8 * r;
            stage[rl * 132 + cl] = (f2sum(acc[i][r]) + b2[cl]) * EPS_VAL;
        }
    __syncthreads();

    #pragma unroll
    for (int it = 0; it < 4; it++) {
        int idx = tid + it * 256;
        int r = idx >> 5;
        int c = (idx & 31) << 2;
        int e = e0 + r;
        if (e < E)
            *(float4*)(out + (size_t)e * 128 + c) = *(float4*)(stage + r * 132 + c);
    }
}

// ---------------------------------------------------------------------------
extern "C" void kernel_launch(void* const* d_in, const int* in_sizes, int n_in,
                              void* d_out, int out_size) {
    const float* x  = (const float*)d_in[0];
    const int*   ei = (const int*)d_in[1];     // int32 [2, E]
    const float* W1 = (const float*)d_in[2];
    const float* b1 = (const float*)d_in[3];
    const float* W2 = (const float*)d_in[4];
    const float* b2 = (const float*)d_in[5];
    float* out = (float*)d_out;

    int N = in_sizes[0] / 128;
    int E = in_sizes[1] / 2;

    const int SMEM1 = 2 * 64 * 132 * sizeof(float);          // 67584 B
    const int SMEM2 = (32 * 260 + 128 * 68) * sizeof(float); // 68096 B
    cudaFuncSetAttribute(node_proj_kernel,
                         cudaFuncAttributeMaxDynamicSharedMemorySize, SMEM1);
    cudaFuncSetAttribute(edge_mlp_kernel,
                         cudaFuncAttributeMaxDynamicSharedMemorySize, SMEM2);

    dim3 g1((N + 63) / 64, 4);
    node_proj_kernel<<<g1, 256, SMEM1>>>(x, W1, b1, N);

    int g2 = (E + 31) / 32;
    edge_mlp_kernel<<<g2, 256, SMEM2>>>(ei, W2, b2, out, E);
}

// round 4
// speedup vs baseline: 1.0914x; 1.0914x over previous
#include <cuda_runtime.h>
#include <cuda_bf16.h>
#include <cstdint>
#include <cstddef>

#define EPS_VAL 0.5f
typedef unsigned long long u64;
typedef unsigned int u32;

// ===================== fp32x2 helpers (kernel 1) =====================
__device__ __forceinline__ u64 ffma2(u64 a, u64 b, u64 c) {
    u64 d;
    asm("fma.rn.f32x2 %0, %1, %2, %3;" : "=l"(d) : "l"(a), "l"(b), "l"(c));
    return d;
}
__device__ __forceinline__ float f2sum(u64 v) {
    return __uint_as_float((unsigned)(v & 0xffffffffu)) +
           __uint_as_float((unsigned)(v >> 32));
}

// bf16 mma.sync (sm_80 baseline ISA — legal at family target sm_103)
__device__ __forceinline__ void mma_bf16(float* d, u32 a0, u32 a1, u32 a2, u32 a3,
                                         u32 b0, u32 b1) {
    asm volatile(
        "mma.sync.aligned.m16n8k16.row.col.f32.bf16.bf16.f32 "
        "{%0,%1,%2,%3}, {%4,%5,%6,%7}, {%8,%9}, {%0,%1,%2,%3};"
        : "+f"(d[0]), "+f"(d[1]), "+f"(d[2]), "+f"(d[3])
        : "r"(a0), "r"(a1), "r"(a2), "r"(a3), "r"(b0), "r"(b1));
}

__device__ __forceinline__ u32 pack_bf16x2(__nv_bfloat16 lo, __nv_bfloat16 hi) {
    return (u32)__bfloat16_as_ushort(lo) | ((u32)__bfloat16_as_ushort(hi) << 16);
}

// Scratch: node projections y [N_MAX, 256] fp32
#define N_MAX 100000
__device__ float g_y[(size_t)N_MAX * 256];

// ---------------------------------------------------------------------------
// Kernel 1: y = x @ W1^T + 0.5*b1  (SIMT fp32 f32x2 — passed in R2, exact)
// ---------------------------------------------------------------------------
__global__ __launch_bounds__(256) void node_proj_kernel(
    const float* __restrict__ x, const float* __restrict__ W1,
    const float* __restrict__ b1, int N)
{
    extern __shared__ __align__(16) float sm[];
    float* xs = sm;
    float* ws = sm + 64 * 132;
    float* __restrict__ y = g_y;

    const int tid = threadIdx.x;
    const int n0 = blockIdx.x * 64;
    const int j0 = blockIdx.y * 64;

    #pragma unroll
    for (int it = 0; it < 8; it++) {
        int idx = tid + it * 256;
        int r = idx >> 5, c = (idx & 31) << 2;
        int gr = n0 + r;
        float4 v = make_float4(0.f, 0.f, 0.f, 0.f);
        if (gr < N) v = *(const float4*)(x + (size_t)gr * 128 + c);
        *(float4*)(xs + r * 132 + c) = v;
    }
    #pragma unroll
    for (int it = 0; it < 8; it++) {
        int idx = tid + it * 256;
        int r = idx >> 5, c = (idx & 31) << 2;
        float4 v = *(const float4*)(W1 + (size_t)(j0 + r) * 128 + c);
        *(float4*)(ws + r * 132 + c) = v;
    }
    __syncthreads();

    const int l = tid & 31, w = tid >> 5;
    const int le = l >> 3, lo = l & 7;
    const int we = w & 3,  wo = w >> 2;

    u64 acc[4][4];
    #pragma unroll
    for (int i = 0; i < 4; i++)
        #pragma unroll
        for (int r = 0; r < 4; r++) acc[i][r] = 0ull;

    const float* xbase = xs + (16 * we + le) * 132;
    const float* wbase = ws + (32 * wo + lo) * 132;

    #pragma unroll 2
    for (int k = 0; k < 128; k += 4) {
        ulonglong2 xa[4], wb[4];
        #pragma unroll
        for (int i = 0; i < 4; i++) xa[i] = *(const ulonglong2*)(xbase + (4 * i) * 132 + k);
        #pragma unroll
        for (int r = 0; r < 4; r++) wb[r] = *(const ulonglong2*)(wbase + (8 * r) * 132 + k);
        #pragma unroll
        for (int i = 0; i < 4; i++)
            #pragma unroll
            for (int r = 0; r < 4; r++) {
                acc[i][r] = ffma2(xa[i].x, wb[r].x, acc[i][r]);
                acc[i][r] = ffma2(xa[i].y, wb[r].y, acc[i][r]);
            }
    }
    __syncthreads();

    float* stage = sm;
    #pragma unroll
    for (int i = 0; i < 4; i++)
        #pragma unroll
        for (int r = 0; r < 4; r++) {
            int rl = 16 * we + le + 4 * i;
            int cl = 32 * wo + lo + 8 * r;
            stage[rl * 68 + cl] = f2sum(acc[i][r]) + 0.5f * b1[j0 + cl];
        }
    __syncthreads();

    #pragma unroll
    for (int it = 0; it < 4; it++) {
        int idx = tid + it * 256;
        int r = idx >> 4, c = (idx & 15) << 2;
        int gr = n0 + r;
        if (gr < N)
            *(float4*)(y + (size_t)gr * 256 + j0 + c) = *(float4*)(stage + r * 68 + c);
    }
}

// ---------------------------------------------------------------------------
// Kernel 2: persistent mma.sync bf16 edge GEMM, 3-way split for accuracy.
// Tile M=64 edges x N=128 x K=256. W2 hi/lo resident in smem (once/block);
// h = relu(y_s + y_d) hi/lo regenerated per tile.
// D = Ahi*Bhi + Ahi*Blo + Alo*Bhi  (fp32 accum)
// ---------------------------------------------------------------------------
// smem byte offsets. Row stride 264 bf16 = 528 B (528/4 = 132 == 4 mod 32 ->
// fragment quad loads are bank-conflict-free).
#define SM_B2   0
#define SM_WHI  512
#define SM_WLO  (512 + 67584)
#define SM_HHI  (512 + 2 * 67584)
#define SM_HLO  (512 + 2 * 67584 + 33792)
#define SMEM_EDGE (512 + 2 * 67584 + 2 * 33792)  // 203264 B

__global__ __launch_bounds__(256, 1) void edge_mma_kernel(
    const int* __restrict__ edge_index,
    const float* __restrict__ W2, const float* __restrict__ b2,
    float* __restrict__ out, int E)
{
    extern __shared__ __align__(16) char smem[];
    const float* __restrict__ y = g_y;

    const int tid  = threadIdx.x;
    const int lane = tid & 31;
    const int wid  = tid >> 5;
    const int wm = wid & 1;        // 2 m-warps (32 edges each)
    const int wn = wid >> 1;       // 4 n-warps (32 outs each)
    const int l4 = lane >> 2;      // 0..7 row-in-fragment
    const int l2 = (lane & 3) * 2; // 0,2,4,6 col pair base

    // --- one-time setup: b2 + W2 hi/lo split into smem ---
    if (tid < 128) *(float*)(smem + SM_B2 + tid * 4) = b2[tid];
    for (int idx = tid; idx < 128 * 256; idx += 256) {
        int n = idx >> 8, k = idx & 255;
        float w = W2[idx];
        __nv_bfloat16 hb = __float2bfloat16(w);
        __nv_bfloat16 lb = __float2bfloat16(w - __bfloat162float(hb));
        u32 byte = (u32)n * 528u + (u32)k * 2u;
        *(__nv_bfloat16*)(smem + SM_WHI + byte) = hb;
        *(__nv_bfloat16*)(smem + SM_WLO + byte) = lb;
    }
    __syncthreads();

    const int ntiles = (E + 63) / 64;
    const int r_g = tid >> 2;      // gather: row 0..63
    const int q_g = tid & 3;       // gather: k-quarter 0..3

    for (int t = blockIdx.x; t < ntiles; t += gridDim.x) {
        const int t0 = t * 64;
        __syncthreads();   // previous tile's mma reads of h are done

        // --- gather: h[r][k] = relu(y[s][k] + y[d][k]), split hi/lo ---
        {
            const int e = t0 + r_g;
            const bool valid = (e < E);
            int s = 0, dd = 0;
            if (valid) { s = edge_index[e]; dd = edge_index[E + e]; }
            const float* ys = y + (size_t)s * 256;
            const float* yd = y + (size_t)dd * 256;
            char* hhi_row = smem + SM_HHI + (u32)r_g * 528u;
            char* hlo_row = smem + SM_HLO + (u32)r_g * 528u;
            #pragma unroll 4
            for (int i = 0; i < 16; i++) {
                int k = q_g * 64 + i * 4;
                uint2 hi2 = make_uint2(0u, 0u), lo2 = make_uint2(0u, 0u);
                if (valid) {
                    float4 a = *(const float4*)(ys + k);
                    float4 b = *(const float4*)(yd + k);
                    float h0 = fmaxf(a.x + b.x, 0.f), h1 = fmaxf(a.y + b.y, 0.f);
                    float h2 = fmaxf(a.z + b.z, 0.f), h3 = fmaxf(a.w + b.w, 0.f);
                    __nv_bfloat16 p0 = __float2bfloat16(h0), p1 = __float2bfloat16(h1);
                    __nv_bfloat16 p2 = __float2bfloat16(h2), p3 = __float2bfloat16(h3);
                    hi2.x = pack_bf16x2(p0, p1);
                    hi2.y = pack_bf16x2(p2, p3);
                    lo2.x = pack_bf16x2(__float2bfloat16(h0 - __bfloat162float(p0)),
                                        __float2bfloat16(h1 - __bfloat162float(p1)));
                    lo2.y = pack_bf16x2(__float2bfloat16(h2 - __bfloat162float(p2)),
                                        __float2bfloat16(h3 - __bfloat162float(p3)));
                }
                *(uint2*)(hhi_row + k * 2) = hi2;
                *(uint2*)(hlo_row + k * 2) = lo2;
            }
        }
        __syncthreads();

        // --- mma: 16 k-steps over K=256 ---
        float acc[2][4][4];
        #pragma unroll
        for (int i = 0; i < 2; i++)
            #pragma unroll
            for (int j = 0; j < 4; j++)
                #pragma unroll
                for (int v = 0; v < 4; v++) acc[i][j][v] = 0.f;

        const char* ha_base = smem + SM_HHI + (u32)(wm * 32 + l4) * 528u + (u32)l2 * 2u;
        const char* hl_base = smem + SM_HLO + (u32)(wm * 32 + l4) * 528u + (u32)l2 * 2u;
        const char* bh_base = smem + SM_WHI + (u32)(wn * 32 + l4) * 528u + (u32)l2 * 2u;
        const char* bl_base = smem + SM_WLO + (u32)(wn * 32 + l4) * 528u + (u32)l2 * 2u;

        #pragma unroll 2
        for (int ks = 0; ks < 16; ks++) {
            const u32 kb = (u32)ks * 32u;
            u32 Ah[2][4], Al[2][4], Bh[4][2], Bl[4][2];
            #pragma unroll
            for (int i = 0; i < 2; i++) {
                const char* p  = ha_base + (u32)i * (16u * 528u) + kb;
                const char* pl = hl_base + (u32)i * (16u * 528u) + kb;
                Ah[i][0] = *(const u32*)(p);
                Ah[i][1] = *(const u32*)(p + 8 * 528);
                Ah[i][2] = *(const u32*)(p + 16);
                Ah[i][3] = *(const u32*)(p + 8 * 528 + 16);
                Al[i][0] = *(const u32*)(pl);
                Al[i][1] = *(const u32*)(pl + 8 * 528);
                Al[i][2] = *(const u32*)(pl + 16);
                Al[i][3] = *(const u32*)(pl + 8 * 528 + 16);
            }
            #pragma unroll
            for (int j = 0; j < 4; j++) {
                const char* p  = bh_base + (u32)j * (8u * 528u) + kb;
                const char* pl = bl_base + (u32)j * (8u * 528u) + kb;
                Bh[j][0] = *(const u32*)(p);
                Bh[j][1] = *(const u32*)(p + 16);
                Bl[j][0] = *(const u32*)(pl);
                Bl[j][1] = *(const u32*)(pl + 16);
            }
            #pragma unroll
            for (int i = 0; i < 2; i++)
                #pragma unroll
                for (int j = 0; j < 4; j++) {
                    mma_bf16(acc[i][j], Ah[i][0], Ah[i][1], Ah[i][2], Ah[i][3],
                             Bh[j][0], Bh[j][1]);
                    mma_bf16(acc[i][j], Ah[i][0], Ah[i][1], Ah[i][2], Ah[i][3],
                             Bl[j][0], Bl[j][1]);
                    mma_bf16(acc[i][j], Al[i][0], Al[i][1], Al[i][2], Al[i][3],
                             Bh[j][0], Bh[j][1]);
                }
        }

        // --- epilogue: bias + EPS, direct float2 stores ---
        #pragma unroll
        for (int i = 0; i < 2; i++) {
            #pragma unroll
            for (int j = 0; j < 4; j++) {
                int col = wn * 32 + j * 8 + l2;
                float bb0 = *(const float*)(smem + SM_B2 + col * 4);
                float bb1 = *(const float*)(smem + SM_B2 + (col + 1) * 4);
                int r0 = t0 + wm * 32 + i * 16 + l4;
                if (r0 < E) {
                    float2 v;
                    v.x = (acc[i][j][0] + bb0) * EPS_VAL;
                    v.y = (acc[i][j][1] + bb1) * EPS_VAL;
                    *(float2*)(out + (size_t)r0 * 128 + col) = v;
                }
                int r1 = r0 + 8;
                if (r1 < E) {
                    float2 v;
                    v.x = (acc[i][j][2] + bb0) * EPS_VAL;
                    v.y = (acc[i][j][3] + bb1) * EPS_VAL;
                    *(float2*)(out + (size_t)r1 * 128 + col) = v;
                }
            }
        }
    }
}

// ---------------------------------------------------------------------------
extern "C" void kernel_launch(void* const* d_in, const int* in_sizes, int n_in,
                              void* d_out, int out_size) {
    const float* x  = (const float*)d_in[0];
    const int*   ei = (const int*)d_in[1];     // int32 [2, E]
    const float* W1 = (const float*)d_in[2];
    const float* b1 = (const float*)d_in[3];
    const float* W2 = (const float*)d_in[4];
    const float* b2 = (const float*)d_in[5];
    float* out = (float*)d_out;

    int N = in_sizes[0] / 128;
    int E = in_sizes[1] / 2;

    const int SMEM1 = 2 * 64 * 132 * sizeof(float);
    cudaFuncSetAttribute(node_proj_kernel,
                         cudaFuncAttributeMaxDynamicSharedMemorySize, SMEM1);
    cudaFuncSetAttribute(edge_mma_kernel,
                         cudaFuncAttributeMaxDynamicSharedMemorySize, SMEM_EDGE);

    dim3 g1((N + 63) / 64, 4);
    node_proj_kernel<<<g1, 256, SMEM1>>>(x, W1, b1, N);

    edge_mma_kernel<<<152, 256, SMEM_EDGE>>>(ei, W2, b2, out, E);
}

// round 5
// speedup vs baseline: 1.1412x; 1.0457x over previous
#include <cuda_runtime.h>
#include <cuda_bf16.h>
#include <cstdint>
#include <cstddef>

#define EPS_VAL 0.5f
typedef unsigned long long u64;
typedef unsigned int u32;

// ===================== helpers =====================
__device__ __forceinline__ u64 ffma2(u64 a, u64 b, u64 c) {
    u64 d;
    asm("fma.rn.f32x2 %0, %1, %2, %3;" : "=l"(d) : "l"(a), "l"(b), "l"(c));
    return d;
}
__device__ __forceinline__ float f2sum(u64 v) {
    return __uint_as_float((unsigned)(v & 0xffffffffu)) +
           __uint_as_float((unsigned)(v >> 32));
}
__device__ __forceinline__ void mma_bf16(float* d, const u32* a, u32 b0, u32 b1) {
    asm volatile(
        "mma.sync.aligned.m16n8k16.row.col.f32.bf16.bf16.f32 "
        "{%0,%1,%2,%3}, {%4,%5,%6,%7}, {%8,%9}, {%0,%1,%2,%3};"
        : "+f"(d[0]), "+f"(d[1]), "+f"(d[2]), "+f"(d[3])
        : "r"(a[0]), "r"(a[1]), "r"(a[2]), "r"(a[3]), "r"(b0), "r"(b1));
}
__device__ __forceinline__ void ldmx4(u32* r, u32 addr) {
    asm volatile("ldmatrix.sync.aligned.m8n8.x4.shared.b16 {%0,%1,%2,%3}, [%4];"
        : "=r"(r[0]), "=r"(r[1]), "=r"(r[2]), "=r"(r[3]) : "r"(addr));
}
__device__ __forceinline__ u32 smem_u32(const void* p) {
    u32 a;
    asm("{ .reg .u64 t; cvta.to.shared.u64 t, %1; cvt.u32.u64 %0, t; }"
        : "=r"(a) : "l"(p));
    return a;
}
__device__ __forceinline__ u32 pack_bf16x2(__nv_bfloat16 lo, __nv_bfloat16 hi) {
    return (u32)__bfloat16_as_ushort(lo) | ((u32)__bfloat16_as_ushort(hi) << 16);
}

// Scratch: node projections y [N_MAX, 256] fp32
#define N_MAX 100000
__device__ float g_y[(size_t)N_MAX * 256];

// ---------------------------------------------------------------------------
// Kernel 1: y = x @ W1^T + 0.5*b1  (SIMT fp32 f32x2 — exact; unchanged)
// ---------------------------------------------------------------------------
__global__ __launch_bounds__(256) void node_proj_kernel(
    const float* __restrict__ x, const float* __restrict__ W1,
    const float* __restrict__ b1, int N)
{
    extern __shared__ __align__(16) float sm[];
    float* xs = sm;
    float* ws = sm + 64 * 132;
    float* __restrict__ y = g_y;

    const int tid = threadIdx.x;
    const int n0 = blockIdx.x * 64;
    const int j0 = blockIdx.y * 64;

    #pragma unroll
    for (int it = 0; it < 8; it++) {
        int idx = tid + it * 256;
        int r = idx >> 5, c = (idx & 31) << 2;
        int gr = n0 + r;
        float4 v = make_float4(0.f, 0.f, 0.f, 0.f);
        if (gr < N) v = *(const float4*)(x + (size_t)gr * 128 + c);
        *(float4*)(xs + r * 132 + c) = v;
    }
    #pragma unroll
    for (int it = 0; it < 8; it++) {
        int idx = tid + it * 256;
        int r = idx >> 5, c = (idx & 31) << 2;
        float4 v = *(const float4*)(W1 + (size_t)(j0 + r) * 128 + c);
        *(float4*)(ws + r * 132 + c) = v;
    }
    __syncthreads();

    const int l = tid & 31, w = tid >> 5;
    const int le = l >> 3, lo = l & 7;
    const int we = w & 3,  wo = w >> 2;

    u64 acc[4][4];
    #pragma unroll
    for (int i = 0; i < 4; i++)
        #pragma unroll
        for (int r = 0; r < 4; r++) acc[i][r] = 0ull;

    const float* xbase = xs + (16 * we + le) * 132;
    const float* wbase = ws + (32 * wo + lo) * 132;

    #pragma unroll 2
    for (int k = 0; k < 128; k += 4) {
        ulonglong2 xa[4], wb[4];
        #pragma unroll
        for (int i = 0; i < 4; i++) xa[i] = *(const ulonglong2*)(xbase + (4 * i) * 132 + k);
        #pragma unroll
        for (int r = 0; r < 4; r++) wb[r] = *(const ulonglong2*)(wbase + (8 * r) * 132 + k);
        #pragma unroll
        for (int i = 0; i < 4; i++)
            #pragma unroll
            for (int r = 0; r < 4; r++) {
                acc[i][r] = ffma2(xa[i].x, wb[r].x, acc[i][r]);
                acc[i][r] = ffma2(xa[i].y, wb[r].y, acc[i][r]);
            }
    }
    __syncthreads();

    float* stage = sm;
    #pragma unroll
    for (int i = 0; i < 4; i++)
        #pragma unroll
        for (int r = 0; r < 4; r++) {
            int rl = 16 * we + le + 4 * i;
            int cl = 32 * wo + lo + 8 * r;
            stage[rl * 68 + cl] = f2sum(acc[i][r]) + 0.5f * b1[j0 + cl];
        }
    __syncthreads();

    #pragma unroll
    for (int it = 0; it < 4; it++) {
        int idx = tid + it * 256;
        int r = idx >> 4, c = (idx & 15) << 2;
        int gr = n0 + r;
        if (gr < N)
            *(float4*)(y + (size_t)gr * 256 + j0 + c) = *(float4*)(stage + r * 68 + c);
    }
}

// ---------------------------------------------------------------------------
// Kernel 2: persistent mma.sync bf16 edge GEMM, software-pipelined.
// 512 threads. Tile M=64 x N=128 x K=256. Warp grid 4m x 4n (16 rows x 32 cols).
// ldmatrix fragment loads; gather of next tile held raw in registers.
// D = Ahi*Bhi + Ahi*Blo + Alo*Bhi  (fp32 accum)
// ---------------------------------------------------------------------------
// smem byte offsets; row stride 528 B (= 33*16B -> conflict-free ldmatrix).
#define SM_B2   0
#define SM_WHI  512
#define SM_WLO  (512 + 67584)
#define SM_HHI  (512 + 2 * 67584)
#define SM_HLO  (512 + 2 * 67584 + 33792)
#define SMEM_EDGE (512 + 2 * 67584 + 2 * 33792)  // 203264 B

__device__ __forceinline__ void gather_raw(
    const int* __restrict__ edge_index, const float* __restrict__ y,
    int t, int E, int r_g, int q_g, float* a, float* b)
{
    const int e = t * 64 + r_g;
    if (e < E) {
        int s  = edge_index[e];
        int dd = edge_index[E + e];
        const float* ys = y + (size_t)s * 256 + q_g * 32;
        const float* yd = y + (size_t)dd * 256 + q_g * 32;
        #pragma unroll
        for (int i = 0; i < 8; i++) {
            float4 va = *(const float4*)(ys + 4 * i);
            float4 vb = *(const float4*)(yd + 4 * i);
            a[4*i] = va.x; a[4*i+1] = va.y; a[4*i+2] = va.z; a[4*i+3] = va.w;
            b[4*i] = vb.x; b[4*i+1] = vb.y; b[4*i+2] = vb.z; b[4*i+3] = vb.w;
        }
    } else {
        #pragma unroll
        for (int i = 0; i < 32; i++) { a[i] = 0.f; b[i] = 0.f; }
    }
}

__global__ __launch_bounds__(512, 1) void edge_mma_kernel(
    const int* __restrict__ edge_index,
    const float* __restrict__ W2, const float* __restrict__ b2,
    float* __restrict__ out, int E)
{
    extern __shared__ __align__(16) char smem[];
    const float* __restrict__ y = g_y;
    const u32 sbase = smem_u32(smem);

    const int tid  = threadIdx.x;
    const int lane = tid & 31;
    const int wid  = tid >> 5;
    const int wm = wid & 3;        // 4 m-warps (16 rows each)
    const int wn = wid >> 2;       // 4 n-warps (32 cols each)

    // --- one-time setup: b2 + W2 hi/lo split into smem ---
    if (tid < 128) *(float*)(smem + SM_B2 + tid * 4) = b2[tid];
    for (int idx = tid; idx < 128 * 256; idx += 512) {
        int n = idx >> 8, k = idx & 255;
        float w = W2[idx];
        __nv_bfloat16 hb = __float2bfloat16(w);
        __nv_bfloat16 lb = __float2bfloat16(w - __bfloat162float(hb));
        u32 byte = (u32)n * 528u + (u32)k * 2u;
        *(__nv_bfloat16*)(smem + SM_WHI + byte) = hb;
        *(__nv_bfloat16*)(smem + SM_WLO + byte) = lb;
    }

    // ldmatrix per-lane address offsets (within a 16x16 bf16 tile, stride 528)
    // A (m16 x k16, x4): row = lane&15, k-half = lane>>4
    const u32 aoff = (u32)(lane & 15) * 528u + (u32)(lane >> 4) * 16u;
    // B (n16 x k16, x4): n = (lane&7) + ((lane&16)?8:0), k-half = (lane>>3)&1
    const u32 boff = ((u32)(lane & 7) + (u32)((lane >> 4) & 1) * 8u) * 528u
                   + (u32)((lane >> 3) & 1) * 16u;

    const u32 sa_hi = sbase + SM_HHI + (u32)(wm * 16) * 528u + aoff;
    const u32 sa_lo = sbase + SM_HLO + (u32)(wm * 16) * 528u + aoff;
    const u32 sb_hi = sbase + SM_WHI + (u32)(wn * 32) * 528u + boff;
    const u32 sb_lo = sbase + SM_WLO + (u32)(wn * 32) * 528u + boff;

    const int ntiles = (E + 63) / 64;
    const int r_g = tid >> 3;      // gather row 0..63
    const int q_g = tid & 7;       // gather k-eighth (32 floats)

    // raw gather registers for the pipelined tile
    float ga[32], gb[32];

    int t = blockIdx.x;
    if (t < ntiles) gather_raw(edge_index, y, t, E, r_g, q_g, ga, gb);
    __syncthreads();   // W2/b2 ready

    for (; t < ntiles; t += gridDim.x) {
        const int t0 = t * 64;

        // --- stage h = relu(ga+gb) hi/lo into smem ---
        {
            char* hhi = smem + SM_HHI + (u32)r_g * 528u + (u32)q_g * 64u;
            char* hlo = smem + SM_HLO + (u32)r_g * 528u + (u32)q_g * 64u;
            #pragma unroll
            for (int i = 0; i < 8; i++) {
                float h0 = fmaxf(ga[4*i+0] + gb[4*i+0], 0.f);
                float h1 = fmaxf(ga[4*i+1] + gb[4*i+1], 0.f);
                float h2 = fmaxf(ga[4*i+2] + gb[4*i+2], 0.f);
                float h3 = fmaxf(ga[4*i+3] + gb[4*i+3], 0.f);
                __nv_bfloat16 p0 = __float2bfloat16(h0), p1 = __float2bfloat16(h1);
                __nv_bfloat16 p2 = __float2bfloat16(h2), p3 = __float2bfloat16(h3);
                uint2 hi2, lo2;
                hi2.x = pack_bf16x2(p0, p1);
                hi2.y = pack_bf16x2(p2, p3);
                lo2.x = pack_bf16x2(__float2bfloat16(h0 - __bfloat162float(p0)),
                                    __float2bfloat16(h1 - __bfloat162float(p1)));
                lo2.y = pack_bf16x2(__float2bfloat16(h2 - __bfloat162float(p2)),
                                    __float2bfloat16(h3 - __bfloat162float(p3)));
                *(uint2*)(hhi + i * 8) = hi2;
                *(uint2*)(hlo + i * 8) = lo2;
            }
        }
        __syncthreads();

        // --- prefetch next tile's raw gather (consumed after full mma loop) ---
        {
            int nxt = t + gridDim.x;
            if (nxt < ntiles) gather_raw(edge_index, y, nxt, E, r_g, q_g, ga, gb);
        }

        // --- mma over K=256 (16 k-steps) ---
        float acc[4][4];
        #pragma unroll
        for (int j = 0; j < 4; j++)
            #pragma unroll
            for (int v = 0; v < 4; v++) acc[j][v] = 0.f;

        #pragma unroll 4
        for (int ks = 0; ks < 16; ks++) {
            const u32 kb = (u32)ks * 32u;
            u32 aH[4], aL[4], bH[8], bL[8];
            ldmx4(aH, sa_hi + kb);
            ldmx4(aL, sa_lo + kb);
            ldmx4(bH,     sb_hi + kb);
            ldmx4(bH + 4, sb_hi + 16u * 528u + kb);
            ldmx4(bL,     sb_lo + kb);
            ldmx4(bL + 4, sb_lo + 16u * 528u + kb);
            #pragma unroll
            for (int j = 0; j < 4; j++) {
                mma_bf16(acc[j], aH, bH[2*j], bH[2*j+1]);
                mma_bf16(acc[j], aH, bL[2*j], bL[2*j+1]);
                mma_bf16(acc[j], aL, bH[2*j], bH[2*j+1]);
            }
        }

        // --- epilogue: bias + EPS, float2 stores ---
        #pragma unroll
        for (int j = 0; j < 4; j++) {
            int col = wn * 32 + j * 8 + (lane & 3) * 2;
            float bb0 = *(const float*)(smem + SM_B2 + col * 4);
            float bb1 = *(const float*)(smem + SM_B2 + (col + 1) * 4);
            int r0 = t0 + wm * 16 + (lane >> 2);
            if (r0 < E) {
                float2 v;
                v.x = (acc[j][0] + bb0) * EPS_VAL;
                v.y = (acc[j][1] + bb1) * EPS_VAL;
                *(float2*)(out + (size_t)r0 * 128 + col) = v;
            }
            int r1 = r0 + 8;
            if (r1 < E) {
                float2 v;
                v.x = (acc[j][2] + bb0) * EPS_VAL;
                v.y = (acc[j][3] + bb1) * EPS_VAL;
                *(float2*)(out + (size_t)r1 * 128 + col) = v;
            }
        }
        __syncthreads();   // all warps done reading h before next staging
    }
}

// ---------------------------------------------------------------------------
extern "C" void kernel_launch(void* const* d_in, const int* in_sizes, int n_in,
                              void* d_out, int out_size) {
    const float* x  = (const float*)d_in[0];
    const int*   ei = (const int*)d_in[1];     // int32 [2, E]
    const float* W1 = (const float*)d_in[2];
    const float* b1 = (const float*)d_in[3];
    const float* W2 = (const float*)d_in[4];
    const float* b2 = (const float*)d_in[5];
    float* out = (float*)d_out;

    int N = in_sizes[0] / 128;
    int E = in_sizes[1] / 2;

    const int SMEM1 = 2 * 64 * 132 * sizeof(float);
    cudaFuncSetAttribute(node_proj_kernel,
                         cudaFuncAttributeMaxDynamicSharedMemorySize, SMEM1);
    cudaFuncSetAttribute(edge_mma_kernel,
                         cudaFuncAttributeMaxDynamicSharedMemorySize, SMEM_EDGE);

    dim3 g1((N + 63) / 64, 4);
    node_proj_kernel<<<g1, 256, SMEM1>>>(x, W1, b1, N);

    edge_mma_kernel<<<152, 512, SMEM_EDGE>>>(ei, W2, b2, out, E);
}

// round 6
// speedup vs baseline: 1.1823x; 1.0360x over previous
#include <cuda_runtime.h>
#include <cuda_bf16.h>
#include <cstdint>
#include <cstddef>

#define EPS_VAL 0.5f
typedef unsigned long long u64;
typedef unsigned int u32;

// ===================== helpers =====================
__device__ __forceinline__ u64 ffma2(u64 a, u64 b, u64 c) {
    u64 d;
    asm("fma.rn.f32x2 %0, %1, %2, %3;" : "=l"(d) : "l"(a), "l"(b), "l"(c));
    return d;
}
__device__ __forceinline__ float f2sum(u64 v) {
    return __uint_as_float((unsigned)(v & 0xffffffffu)) +
           __uint_as_float((unsigned)(v >> 32));
}
__device__ __forceinline__ void mma_bf16(float* d, const u32* a, u32 b0, u32 b1) {
    asm volatile(
        "mma.sync.aligned.m16n8k16.row.col.f32.bf16.bf16.f32 "
        "{%0,%1,%2,%3}, {%4,%5,%6,%7}, {%8,%9}, {%0,%1,%2,%3};"
        : "+f"(d[0]), "+f"(d[1]), "+f"(d[2]), "+f"(d[3])
        : "r"(a[0]), "r"(a[1]), "r"(a[2]), "r"(a[3]), "r"(b0), "r"(b1));
}
__device__ __forceinline__ void ldmx4(u32* r, u32 addr) {
    asm volatile("ldmatrix.sync.aligned.m8n8.x4.shared.b16 {%0,%1,%2,%3}, [%4];"
        : "=r"(r[0]), "=r"(r[1]), "=r"(r[2]), "=r"(r[3]) : "r"(addr));
}
__device__ __forceinline__ u32 smem_u32(const void* p) {
    u32 a;
    asm("{ .reg .u64 t; cvta.to.shared.u64 t, %1; cvt.u32.u64 %0, t; }"
        : "=r"(a) : "l"(p));
    return a;
}
__device__ __forceinline__ u32 pack_bf16x2(__nv_bfloat16 lo, __nv_bfloat16 hi) {
    return (u32)__bfloat16_as_ushort(lo) | ((u32)__bfloat16_as_ushort(hi) << 16);
}
#define BAR_SYNC(id)   asm volatile("bar.sync %0, 384;"   :: "r"(id) : "memory")
#define BAR_ARRIVE(id) asm volatile("bar.arrive %0, 384;" :: "r"(id) : "memory")

// Scratch: node projections y [N_MAX, 256] fp32
#define N_MAX 100000
__device__ float g_y[(size_t)N_MAX * 256];

// ---------------------------------------------------------------------------
// Kernel 1: y = x @ W1^T + 0.5*b1  (SIMT fp32 f32x2 — exact; unchanged)
// ---------------------------------------------------------------------------
__global__ __launch_bounds__(256) void node_proj_kernel(
    const float* __restrict__ x, const float* __restrict__ W1,
    const float* __restrict__ b1, int N)
{
    extern __shared__ __align__(16) float sm[];
    float* xs = sm;
    float* ws = sm + 64 * 132;
    float* __restrict__ y = g_y;

    const int tid = threadIdx.x;
    const int n0 = blockIdx.x * 64;
    const int j0 = blockIdx.y * 64;

    #pragma unroll
    for (int it = 0; it < 8; it++) {
        int idx = tid + it * 256;
        int r = idx >> 5, c = (idx & 31) << 2;
        int gr = n0 + r;
        float4 v = make_float4(0.f, 0.f, 0.f, 0.f);
        if (gr < N) v = *(const float4*)(x + (size_t)gr * 128 + c);
        *(float4*)(xs + r * 132 + c) = v;
    }
    #pragma unroll
    for (int it = 0; it < 8; it++) {
        int idx = tid + it * 256;
        int r = idx >> 5, c = (idx & 31) << 2;
        float4 v = *(const float4*)(W1 + (size_t)(j0 + r) * 128 + c);
        *(float4*)(ws + r * 132 + c) = v;
    }
    __syncthreads();

    const int l = tid & 31, w = tid >> 5;
    const int le = l >> 3, lo = l & 7;
    const int we = w & 3,  wo = w >> 2;

    u64 acc[4][4];
    #pragma unroll
    for (int i = 0; i < 4; i++)
        #pragma unroll
        for (int r = 0; r < 4; r++) acc[i][r] = 0ull;

    const float* xbase = xs + (16 * we + le) * 132;
    const float* wbase = ws + (32 * wo + lo) * 132;

    #pragma unroll 2
    for (int k = 0; k < 128; k += 4) {
        ulonglong2 xa[4], wb[4];
        #pragma unroll
        for (int i = 0; i < 4; i++) xa[i] = *(const ulonglong2*)(xbase + (4 * i) * 132 + k);
        #pragma unroll
        for (int r = 0; r < 4; r++) wb[r] = *(const ulonglong2*)(wbase + (8 * r) * 132 + k);
        #pragma unroll
        for (int i = 0; i < 4; i++)
            #pragma unroll
            for (int r = 0; r < 4; r++) {
                acc[i][r] = ffma2(xa[i].x, wb[r].x, acc[i][r]);
                acc[i][r] = ffma2(xa[i].y, wb[r].y, acc[i][r]);
            }
    }
    __syncthreads();

    float* stage = sm;
    #pragma unroll
    for (int i = 0; i < 4; i++)
        #pragma unroll
        for (int r = 0; r < 4; r++) {
            int rl = 16 * we + le + 4 * i;
            int cl = 32 * wo + lo + 8 * r;
            stage[rl * 68 + cl] = f2sum(acc[i][r]) + 0.5f * b1[j0 + cl];
        }
    __syncthreads();

    #pragma unroll
    for (int it = 0; it < 4; it++) {
        int idx = tid + it * 256;
        int r = idx >> 4, c = (idx & 15) << 2;
        int gr = n0 + r;
        if (gr < N)
            *(float4*)(y + (size_t)gr * 256 + j0 + c) = *(float4*)(stage + r * 68 + c);
    }
}

// ---------------------------------------------------------------------------
// Kernel 2: warp-specialized persistent edge GEMM.
// 384 threads: warps 0-7 consumers (mma), warps 8-11 producers (gather).
// Tile M=32 edges x N=128 x K=256, double-buffered h (hi/lo bf16 split).
// D = Ahi*Bhi + Ahi*Blo + Alo*Bhi  (fp32 accum)
// Named barriers: full[buf]=1+buf, empty[buf]=3+buf, count=384.
// ---------------------------------------------------------------------------
// smem: W2hi [128][264]bf16, W2lo same, then 2 x (Hhi[32][264] + Hlo[32][264])
#define SM_WHI 0
#define SM_WLO 67584
#define SM_H   135168
#define H_BUF_BYTES 33792           // hi (16896) + lo (16896)
#define SMEM_EDGE (135168 + 2 * 33792)  // 202752 B

__global__ __launch_bounds__(384, 1) void edge_mma_kernel(
    const int* __restrict__ edge_index,
    const float* __restrict__ W2, const float* __restrict__ b2,
    float* __restrict__ out, int E)
{
    extern __shared__ __align__(16) char smem[];
    const float* __restrict__ y = g_y;
    const u32 sbase = smem_u32(smem);

    const int tid  = threadIdx.x;
    const int lane = tid & 31;
    const int wid  = tid >> 5;

    // --- one-time: W2 hi/lo split into smem (all threads) ---
    for (int idx = tid; idx < 128 * 256; idx += 384) {
        int n = idx >> 8, k = idx & 255;
        float w = W2[idx];
        __nv_bfloat16 hb = __float2bfloat16(w);
        __nv_bfloat16 lb = __float2bfloat16(w - __bfloat162float(hb));
        u32 byte = (u32)n * 528u + (u32)k * 2u;
        *(__nv_bfloat16*)(smem + SM_WHI + byte) = hb;
        *(__nv_bfloat16*)(smem + SM_WLO + byte) = lb;
    }
    __syncthreads();

    const int ntiles = (E + 31) / 32;

    if (wid < 8) {
        // ================= CONSUMERS (8 warps, 2m x 4n grid) =================
        const int wm = wid & 1;        // 16 rows each
        const int wn = wid >> 1;       // 32 cols each

        const u32 aoff = (u32)(lane & 15) * 528u + (u32)(lane >> 4) * 16u;
        const u32 boff = ((u32)(lane & 7) + (u32)((lane >> 4) & 1) * 8u) * 528u
                       + (u32)((lane >> 3) & 1) * 16u;
        const u32 sb_hi = sbase + SM_WHI + (u32)(wn * 32) * 528u + boff;
        const u32 sb_lo = sb_hi + 67584u;

        // hoist bias (pre-scaled by EPS)
        float bbx[4], bby[4];
        #pragma unroll
        for (int j = 0; j < 4; j++) {
            int col = wn * 32 + j * 8 + (lane & 3) * 2;
            bbx[j] = b2[col] * EPS_VAL;
            bby[j] = b2[col + 1] * EPS_VAL;
        }

        int i = 0;
        for (int t = blockIdx.x; t < ntiles; t += gridDim.x, i++) {
            const int buf = i & 1;
            BAR_SYNC(1 + buf);      // h[buf] filled by producers

            const u32 sa_hi = sbase + SM_H + (u32)buf * H_BUF_BYTES
                            + (u32)(wm * 16) * 528u + aoff;
            const u32 sa_lo = sa_hi + 16896u;

            float acc[4][4];
            #pragma unroll
            for (int j = 0; j < 4; j++)
                #pragma unroll
                for (int v = 0; v < 4; v++) acc[j][v] = 0.f;

            #pragma unroll 4
            for (int ks = 0; ks < 16; ks++) {
                const u32 kb = (u32)ks * 32u;
                u32 aH[4], aL[4], bH[8], bL[8];
                ldmx4(aH, sa_hi + kb);
                ldmx4(aL, sa_lo + kb);
                ldmx4(bH,     sb_hi + kb);
                ldmx4(bH + 4, sb_hi + 16u * 528u + kb);
                ldmx4(bL,     sb_lo + kb);
                ldmx4(bL + 4, sb_lo + 16u * 528u + kb);
                #pragma unroll
                for (int j = 0; j < 4; j++) {
                    mma_bf16(acc[j], aH, bH[2*j], bH[2*j+1]);
                    mma_bf16(acc[j], aH, bL[2*j], bL[2*j+1]);
                    mma_bf16(acc[j], aL, bH[2*j], bH[2*j+1]);
                }
            }
            BAR_ARRIVE(3 + buf);    // h[buf] free (before epilogue: regs only)

            const int t0 = t * 32;
            #pragma unroll
            for (int j = 0; j < 4; j++) {
                int col = wn * 32 + j * 8 + (lane & 3) * 2;
                int r0 = t0 + wm * 16 + (lane >> 2);
                if (r0 < E) {
                    float2 v;
                    v.x = fmaf(acc[j][0], EPS_VAL, bbx[j]);
                    v.y = fmaf(acc[j][1], EPS_VAL, bby[j]);
                    *(float2*)(out + (size_t)r0 * 128 + col) = v;
                }
                int r1 = r0 + 8;
                if (r1 < E) {
                    float2 v;
                    v.x = fmaf(acc[j][2], EPS_VAL, bbx[j]);
                    v.y = fmaf(acc[j][3], EPS_VAL, bby[j]);
                    *(float2*)(out + (size_t)r1 * 128 + col) = v;
                }
            }
        }
    } else {
        // ================= PRODUCERS (4 warps, 128 threads) =================
        const int ptid = tid - 256;
        const int r = ptid >> 2;        // edge row 0..31
        const int q = ptid & 3;         // k-quarter (64 floats)

        int i = 0;
        for (int t = blockIdx.x; t < ntiles; t += gridDim.x, i++) {
            const int buf = i & 1;
            if (i >= 2) BAR_SYNC(3 + buf);   // wait consumers done with h[buf]

            char* hhi = smem + SM_H + buf * H_BUF_BYTES + (u32)r * 528u;
            char* hlo = hhi + 16896;
            const int e = t * 32 + r;
            if (e < E) {
                const int s  = edge_index[e];
                const int dd = edge_index[E + e];
                const float* ys = y + (size_t)s  * 256 + q * 64;
                const float* yd = y + (size_t)dd * 256 + q * 64;
                #pragma unroll
                for (int half = 0; half < 2; half++) {
                    float4 A[8], B[8];
                    #pragma unroll
                    for (int j = 0; j < 8; j++) {
                        A[j] = *(const float4*)(ys + half * 32 + 4 * j);
                        B[j] = *(const float4*)(yd + half * 32 + 4 * j);
                    }
                    #pragma unroll
                    for (int j = 0; j < 8; j++) {
                        float h0 = fmaxf(A[j].x + B[j].x, 0.f);
                        float h1 = fmaxf(A[j].y + B[j].y, 0.f);
                        float h2 = fmaxf(A[j].z + B[j].z, 0.f);
                        float h3 = fmaxf(A[j].w + B[j].w, 0.f);
                        __nv_bfloat16 p0 = __float2bfloat16(h0), p1 = __float2bfloat16(h1);
                        __nv_bfloat16 p2 = __float2bfloat16(h2), p3 = __float2bfloat16(h3);
                        uint2 hi2, lo2;
                        hi2.x = pack_bf16x2(p0, p1);
                        hi2.y = pack_bf16x2(p2, p3);
                        lo2.x = pack_bf16x2(__float2bfloat16(h0 - __bfloat162float(p0)),
                                            __float2bfloat16(h1 - __bfloat162float(p1)));
                        lo2.y = pack_bf16x2(__float2bfloat16(h2 - __bfloat162float(p2)),
                                            __float2bfloat16(h3 - __bfloat162float(p3)));
                        int kidx = q * 64 + half * 32 + 4 * j;
                        *(uint2*)(hhi + kidx * 2) = hi2;
                        *(uint2*)(hlo + kidx * 2) = lo2;
                    }
                }
            } else {
                uint2 z = make_uint2(0u, 0u);
                #pragma unroll
                for (int j = 0; j < 16; j++) {
                    int kidx = q * 64 + 4 * j;
                    *(uint2*)(hhi + kidx * 2) = z;
                    *(uint2*)(hlo + kidx * 2) = z;
                }
            }
            BAR_ARRIVE(1 + buf);    // h[buf] filled
        }
    }
}

// ---------------------------------------------------------------------------
extern "C" void kernel_launch(void* const* d_in, const int* in_sizes, int n_in,
                              void* d_out, int out_size) {
    const float* x  = (const float*)d_in[0];
    const int*   ei = (const int*)d_in[1];     // int32 [2, E]
    const float* W1 = (const float*)d_in[2];
    const float* b1 = (const float*)d_in[3];
    const float* W2 = (const float*)d_in[4];
    const float* b2 = (const float*)d_in[5];
    float* out = (float*)d_out;

    int N = in_sizes[0] / 128;
    int E = in_sizes[1] / 2;

    const int SMEM1 = 2 * 64 * 132 * sizeof(float);
    cudaFuncSetAttribute(node_proj_kernel,
                         cudaFuncAttributeMaxDynamicSharedMemorySize, SMEM1);
    cudaFuncSetAttribute(edge_mma_kernel,
                         cudaFuncAttributeMaxDynamicSharedMemorySize, SMEM_EDGE);

    dim3 g1((N + 63) / 64, 4);
    node_proj_kernel<<<g1, 256, SMEM1>>>(x, W1, b1, N);

    edge_mma_kernel<<<152, 384, SMEM_EDGE>>>(ei, W2, b2, out, E);
}

// round 7
// speedup vs baseline: 1.7103x; 1.4466x over previous
#include <cuda_runtime.h>
#include <cuda_bf16.h>
#include <cstdint>
#include <cstddef>

#define EPS_VAL 0.5f
typedef unsigned long long u64;
typedef unsigned int u32;

// ===================== helpers =====================
__device__ __forceinline__ u64 ffma2(u64 a, u64 b, u64 c) {
    u64 d;
    asm("fma.rn.f32x2 %0, %1, %2, %3;" : "=l"(d) : "l"(a), "l"(b), "l"(c));
    return d;
}
__device__ __forceinline__ float f2sum(u64 v) {
    return __uint_as_float((unsigned)(v & 0xffffffffu)) +
           __uint_as_float((unsigned)(v >> 32));
}
__device__ __forceinline__ void mma_bf16(float* d, const u32* a, u32 b0, u32 b1) {
    asm volatile(
        "mma.sync.aligned.m16n8k16.row.col.f32.bf16.bf16.f32 "
        "{%0,%1,%2,%3}, {%4,%5,%6,%7}, {%8,%9}, {%0,%1,%2,%3};"
        : "+f"(d[0]), "+f"(d[1]), "+f"(d[2]), "+f"(d[3])
        : "r"(a[0]), "r"(a[1]), "r"(a[2]), "r"(a[3]), "r"(b0), "r"(b1));
}
__device__ __forceinline__ void ldmx4(u32* r, u32 addr) {
    asm volatile("ldmatrix.sync.aligned.m8n8.x4.shared.b16 {%0,%1,%2,%3}, [%4];"
        : "=r"(r[0]), "=r"(r[1]), "=r"(r[2]), "=r"(r[3]) : "r"(addr));
}
__device__ __forceinline__ u32 smem_u32(const void* p) {
    u32 a;
    asm("{ .reg .u64 t; cvta.to.shared.u64 t, %1; cvt.u32.u64 %0, t; }"
        : "=r"(a) : "l"(p));
    return a;
}
__device__ __forceinline__ u32 pack_bf16x2(__nv_bfloat16 lo, __nv_bfloat16 hi) {
    return (u32)__bfloat16_as_ushort(lo) | ((u32)__bfloat16_as_ushort(hi) << 16);
}
#define BAR_SYNC(id)   asm volatile("bar.sync %0, 512;"   :: "r"(id) : "memory")
#define BAR_ARRIVE(id) asm volatile("bar.arrive %0, 512;" :: "r"(id) : "memory")

// Scratch: node projections y [N_MAX, 256] fp32
#define N_MAX 100000
__device__ float g_y[(size_t)N_MAX * 256];

// ---------------------------------------------------------------------------
// Kernel 1: y = x @ W1^T + 0.5*b1  (SIMT fp32 f32x2 — exact; unchanged)
// ---------------------------------------------------------------------------
__global__ __launch_bounds__(256) void node_proj_kernel(
    const float* __restrict__ x, const float* __restrict__ W1,
    const float* __restrict__ b1, int N)
{
    extern __shared__ __align__(16) float sm[];
    float* xs = sm;
    float* ws = sm + 64 * 132;
    float* __restrict__ y = g_y;

    const int tid = threadIdx.x;
    const int n0 = blockIdx.x * 64;
    const int j0 = blockIdx.y * 64;

    #pragma unroll
    for (int it = 0; it < 8; it++) {
        int idx = tid + it * 256;
        int r = idx >> 5, c = (idx & 31) << 2;
        int gr = n0 + r;
        float4 v = make_float4(0.f, 0.f, 0.f, 0.f);
        if (gr < N) v = *(const float4*)(x + (size_t)gr * 128 + c);
        *(float4*)(xs + r * 132 + c) = v;
    }
    #pragma unroll
    for (int it = 0; it < 8; it++) {
        int idx = tid + it * 256;
        int r = idx >> 5, c = (idx & 31) << 2;
        float4 v = *(const float4*)(W1 + (size_t)(j0 + r) * 128 + c);
        *(float4*)(ws + r * 132 + c) = v;
    }
    __syncthreads();

    const int l = tid & 31, w = tid >> 5;
    const int le = l >> 3, lo = l & 7;
    const int we = w & 3,  wo = w >> 2;

    u64 acc[4][4];
    #pragma unroll
    for (int i = 0; i < 4; i++)
        #pragma unroll
        for (int r = 0; r < 4; r++) acc[i][r] = 0ull;

    const float* xbase = xs + (16 * we + le) * 132;
    const float* wbase = ws + (32 * wo + lo) * 132;

    #pragma unroll 2
    for (int k = 0; k < 128; k += 4) {
        ulonglong2 xa[4], wb[4];
        #pragma unroll
        for (int i = 0; i < 4; i++) xa[i] = *(const ulonglong2*)(xbase + (4 * i) * 132 + k);
        #pragma unroll
        for (int r = 0; r < 4; r++) wb[r] = *(const ulonglong2*)(wbase + (8 * r) * 132 + k);
        #pragma unroll
        for (int i = 0; i < 4; i++)
            #pragma unroll
            for (int r = 0; r < 4; r++) {
                acc[i][r] = ffma2(xa[i].x, wb[r].x, acc[i][r]);
                acc[i][r] = ffma2(xa[i].y, wb[r].y, acc[i][r]);
            }
    }
    __syncthreads();

    float* stage = sm;
    #pragma unroll
    for (int i = 0; i < 4; i++)
        #pragma unroll
        for (int r = 0; r < 4; r++) {
            int rl = 16 * we + le + 4 * i;
            int cl = 32 * wo + lo + 8 * r;
            stage[rl * 68 + cl] = f2sum(acc[i][r]) + 0.5f * b1[j0 + cl];
        }
    __syncthreads();

    #pragma unroll
    for (int it = 0; it < 4; it++) {
        int idx = tid + it * 256;
        int r = idx >> 4, c = (idx & 15) << 2;
        int gr = n0 + r;
        if (gr < N)
            *(float4*)(y + (size_t)gr * 256 + j0 + c) = *(float4*)(stage + r * 68 + c);
    }
}

// ---------------------------------------------------------------------------
// Kernel 2: warp-specialized persistent edge GEMM, K-chunk pipelined.
// 512 threads: warps 0-7 consumers (m32n32 over M=64 x N=128), warps 8-15
// producers. K=256 split into 4 chunks of 64; h chunk buffers 4-deep.
// D = Ahi*Bhi + Ahi*Blo + Alo*Bhi  (fp32 accum)
// Named barriers (count 512): full[buf]=1+buf, empty[buf]=5+buf, buf=g&3.
// ---------------------------------------------------------------------------
// smem: W2hi [128][264]bf16 (67584), W2lo (67584),
//       4 x h-chunk buf: hi [64 rows][72 bf16] (9216) + lo (9216) = 18432
#define SM_WHI 0
#define SM_WLO 67584
#define SM_H   135168
#define HBUF   18432
#define HSTRIDE 144              // bytes per row (72 bf16): 36 words == 4 mod 32
#define SMEM_EDGE (135168 + 4 * 18432)   // 208896 B

__global__ __launch_bounds__(512, 1) void edge_mma_kernel(
    const int* __restrict__ edge_index,
    const float* __restrict__ W2, const float* __restrict__ b2,
    float* __restrict__ out, int E)
{
    extern __shared__ __align__(16) char smem[];
    const float* __restrict__ y = g_y;
    const u32 sbase = smem_u32(smem);

    const int tid  = threadIdx.x;
    const int lane = tid & 31;
    const int wid  = tid >> 5;

    // --- one-time: W2 hi/lo split into smem (all threads) ---
    for (int idx = tid; idx < 128 * 256; idx += 512) {
        int n = idx >> 8, k = idx & 255;
        float w = W2[idx];
        __nv_bfloat16 hb = __float2bfloat16(w);
        __nv_bfloat16 lb = __float2bfloat16(w - __bfloat162float(hb));
        u32 byte = (u32)n * 528u + (u32)k * 2u;
        *(__nv_bfloat16*)(smem + SM_WHI + byte) = hb;
        *(__nv_bfloat16*)(smem + SM_WLO + byte) = lb;
    }
    __syncthreads();

    const int ntiles = (E + 63) / 64;

    if (wid < 8) {
        // ============ CONSUMERS: 8 warps, 2m x 4n, each m32 x n32 ============
        const int wm = wid & 1;       // 32-row group
        const int wn = wid >> 1;      // 32-col group

        const u32 aoff = (u32)(lane & 15) * HSTRIDE + (u32)(lane >> 4) * 16u;
        const u32 boff = ((u32)(lane & 7) + (u32)((lane >> 4) & 1) * 8u) * 528u
                       + (u32)((lane >> 3) & 1) * 16u;
        const u32 sbH = sbase + SM_WHI + (u32)(wn * 32) * 528u + boff;
        const u32 sbL = sbH + 67584u;

        // bias, pre-scaled
        float bbx[4], bby[4];
        #pragma unroll
        for (int j = 0; j < 4; j++) {
            int col = wn * 32 + j * 8 + (lane & 3) * 2;
            bbx[j] = b2[col] * EPS_VAL;
            bby[j] = b2[col + 1] * EPS_VAL;
        }

        int g = 0;
        for (int t = blockIdx.x; t < ntiles; t += gridDim.x) {
            float acc[2][4][4];
            #pragma unroll
            for (int mt = 0; mt < 2; mt++)
                #pragma unroll
                for (int j = 0; j < 4; j++)
                    #pragma unroll
                    for (int v = 0; v < 4; v++) acc[mt][j][v] = 0.f;

            for (int c = 0; c < 4; c++, g++) {
                const int buf = g & 3;
                BAR_SYNC(1 + buf);

                const u32 saH = sbase + SM_H + (u32)buf * HBUF
                              + (u32)(wm * 32) * HSTRIDE + aoff;
                const u32 saL = saH + 9216u;
                const u32 kbB = (u32)(c * 4) * 32u;

                #pragma unroll
                for (int ks = 0; ks < 4; ks++) {
                    const u32 ka = (u32)ks * 32u;
                    const u32 kb = kbB + ka;
                    u32 aH[2][4], aL[2][4], bH[8], bL[8];
                    ldmx4(aH[0], saH + ka);
                    ldmx4(aH[1], saH + 16u * HSTRIDE + ka);
                    ldmx4(aL[0], saL + ka);
                    ldmx4(aL[1], saL + 16u * HSTRIDE + ka);
                    ldmx4(bH,     sbH + kb);
                    ldmx4(bH + 4, sbH + 16u * 528u + kb);
                    ldmx4(bL,     sbL + kb);
                    ldmx4(bL + 4, sbL + 16u * 528u + kb);
                    #pragma unroll
                    for (int mt = 0; mt < 2; mt++)
                        #pragma unroll
                        for (int j = 0; j < 4; j++) {
                            mma_bf16(acc[mt][j], aH[mt], bH[2*j], bH[2*j+1]);
                            mma_bf16(acc[mt][j], aH[mt], bL[2*j], bL[2*j+1]);
                            mma_bf16(acc[mt][j], aL[mt], bH[2*j], bH[2*j+1]);
                        }
                }
                BAR_ARRIVE(5 + buf);
            }

            // epilogue
            const int t0 = t * 64;
            #pragma unroll
            for (int mt = 0; mt < 2; mt++)
                #pragma unroll
                for (int j = 0; j < 4; j++) {
                    int col = wn * 32 + j * 8 + (lane & 3) * 2;
                    int r0 = t0 + wm * 32 + mt * 16 + (lane >> 2);
                    if (r0 < E) {
                        float2 v;
                        v.x = fmaf(acc[mt][j][0], EPS_VAL, bbx[j]);
                        v.y = fmaf(acc[mt][j][1], EPS_VAL, bby[j]);
                        *(float2*)(out + (size_t)r0 * 128 + col) = v;
                    }
                    int r1 = r0 + 8;
                    if (r1 < E) {
                        float2 v;
                        v.x = fmaf(acc[mt][j][2], EPS_VAL, bbx[j]);
                        v.y = fmaf(acc[mt][j][3], EPS_VAL, bby[j]);
                        *(float2*)(out + (size_t)r1 * 128 + col) = v;
                    }
                }
        }
    } else {
        // ============ PRODUCERS: 8 warps (256 threads) ============
        const int ptid = tid - 256;
        const int r = ptid >> 2;      // edge row 0..63
        const int q = ptid & 3;       // 16-float sub-chunk

        int g = 0;
        for (int t = blockIdx.x; t < ntiles; t += gridDim.x) {
            const int e = t * 64 + r;
            const bool valid = (e < E);
            int s = 0, dd = 0;
            if (valid) { s = edge_index[e]; dd = edge_index[E + e]; }
            const float* ys = y + (size_t)s  * 256 + q * 16;
            const float* yd = y + (size_t)dd * 256 + q * 16;

            for (int c = 0; c < 4; c++, g++) {
                const int buf = g & 3;
                if (g >= 4) BAR_SYNC(5 + buf);

                if (valid) {
                    float4 A[4], B[4];
                    #pragma unroll
                    for (int j = 0; j < 4; j++) {
                        A[j] = *(const float4*)(ys + c * 64 + 4 * j);
                        B[j] = *(const float4*)(yd + c * 64 + 4 * j);
                    }
                    u32 hi[8], lo[8];
                    #pragma unroll
                    for (int j = 0; j < 4; j++) {
                        float h0 = fmaxf(A[j].x + B[j].x, 0.f);
                        float h1 = fmaxf(A[j].y + B[j].y, 0.f);
                        float h2 = fmaxf(A[j].z + B[j].z, 0.f);
                        float h3 = fmaxf(A[j].w + B[j].w, 0.f);
                        __nv_bfloat16 p0 = __float2bfloat16(h0), p1 = __float2bfloat16(h1);
                        __nv_bfloat16 p2 = __float2bfloat16(h2), p3 = __float2bfloat16(h3);
                        hi[2*j]   = pack_bf16x2(p0, p1);
                        hi[2*j+1] = pack_bf16x2(p2, p3);
                        lo[2*j]   = pack_bf16x2(__float2bfloat16(h0 - __bfloat162float(p0)),
                                                __float2bfloat16(h1 - __bfloat162float(p1)));
                        lo[2*j+1] = pack_bf16x2(__float2bfloat16(h2 - __bfloat162float(p2)),
                                                __float2bfloat16(h3 - __bfloat162float(p3)));
                    }
                    char* hhi = smem + SM_H + buf * HBUF + r * HSTRIDE + q * 32;
                    char* hlo = hhi + 9216;
                    *(uint4*)(hhi)      = make_uint4(hi[0], hi[1], hi[2], hi[3]);
                    *(uint4*)(hhi + 16) = make_uint4(hi[4], hi[5], hi[6], hi[7]);
                    *(uint4*)(hlo)      = make_uint4(lo[0], lo[1], lo[2], lo[3]);
                    *(uint4*)(hlo + 16) = make_uint4(lo[4], lo[5], lo[6], lo[7]);
                }
                BAR_ARRIVE(1 + buf);
            }
        }
    }
}

// ---------------------------------------------------------------------------
extern "C" void kernel_launch(void* const* d_in, const int* in_sizes, int n_in,
                              void* d_out, int out_size) {
    const float* x  = (const float*)d_in[0];
    const int*   ei = (const int*)d_in[1];     // int32 [2, E]
    const float* W1 = (const float*)d_in[2];
    const float* b1 = (const float*)d_in[3];
    const float* W2 = (const float*)d_in[4];
    const float* b2 = (const float*)d_in[5];
    float* out = (float*)d_out;

    int N = in_sizes[0] / 128;
    int E = in_sizes[1] / 2;

    const int SMEM1 = 2 * 64 * 132 * sizeof(float);
    cudaFuncSetAttribute(node_proj_kernel,
                         cudaFuncAttributeMaxDynamicSharedMemorySize, SMEM1);
    cudaFuncSetAttribute(edge_mma_kernel,
                         cudaFuncAttributeMaxDynamicSharedMemorySize, SMEM_EDGE);

    dim3 g1((N + 63) / 64, 4);
    node_proj_kernel<<<g1, 256, SMEM1>>>(x, W1, b1, N);

    edge_mma_kernel<<<152, 512, SMEM_EDGE>>>(ei, W2, b2, out, E);
}